// round 15
// baseline (speedup 1.0000x reference)
#include <cuda_runtime.h>

// HopfieldNetwork: B=8, N=4096, ITERS=10 asynchronous sweeps.
// R15: TWO samples per 512-thread block. Each round: decode+flip sample A,
// decode+flip sample B, ONE __syncthreads -- the per-round fixed cost (BAR,
// replicated decode, loop) is amortized over 2 flips, and A's memory/redux
// latencies overlap B's issue. All sweeps' neuron->position tables are
// precomputed into dynamic smem (2 x iters x 4096 u16 = 164KB) so sweep
// transitions need no barrier. Per-sample flip protocol identical to R13
// (static per-sweep keys, thr filter, register spec row from 2nd candidate).
// z int64 scale 2^40; wq = rn(W*2^40); flip delta = +-2*wq via IMAD.WIDE.

constexpr int NN  = 4096;
constexpr int TPB = 512;
constexpr int ZPT = 8;
constexpr int INF = 0x7FFFFFFF;

__device__ long long g_z[8 * NN];                      // z, int64, scale 2^40
__device__ __align__(16) int g_Wq[NN * NN];            // rn(W * 2^40)
__device__ __align__(16) unsigned char g_xsign[NN];    // bit b = (x[b][c] < 0)

// ---------------------------------------------------------------------------
__global__ void __launch_bounds__(256) prep_wq(const float* __restrict__ W,
                                               const float* __restrict__ x,
                                               int B)
{
    const int base = (blockIdx.x * 256 + threadIdx.x) * 16;
    const float4* w4 = reinterpret_cast<const float4*>(W + base);
    int4* o4 = reinterpret_cast<int4*>(g_Wq + base);
#pragma unroll
    for (int g = 0; g < 4; g++) {
        const float4 v = w4[g];
        int4 o;
        o.x = __float2int_rn(v.x * 0x1.0p40f);
        o.y = __float2int_rn(v.y * 0x1.0p40f);
        o.z = __float2int_rn(v.z * 0x1.0p40f);
        o.w = __float2int_rn(v.w * 0x1.0p40f);
        o4[g] = o;
    }
    if (blockIdx.x == 0) {
        for (int c = threadIdx.x * 16; c < threadIdx.x * 16 + 16; c++) {
            unsigned v = 0;
#pragma unroll
            for (int b = 0; b < 8; b++)
                if (b < B && x[(size_t)b * NN + c] < 0.f) v |= 1u << b;
            g_xsign[c] = (unsigned char)v;
        }
    }
}

// ---------------------------------------------------------------------------
__global__ void __launch_bounds__(256) gemv_init(int B)
{
    const int row  = blockIdx.x;
    const int tid  = threadIdx.x;
    const int base = tid * 16;
    const int lane = tid & 31, wid = tid >> 5;

    const uint4 sb4 = *reinterpret_cast<const uint4*>(g_xsign + base);
    const unsigned sb[4] = {sb4.x, sb4.y, sb4.z, sb4.w};

    const int4* w4 = reinterpret_cast<const int4*>(g_Wq + (size_t)row * NN + base);
    const int4 wa = w4[0], wb = w4[1], wc = w4[2], wd = w4[3];
    const int wq[16] = {wa.x, wa.y, wa.z, wa.w,  wb.x, wb.y, wb.z, wb.w,
                        wc.x, wc.y, wc.z, wc.w,  wd.x, wd.y, wd.z, wd.w};

    long long acc[8];
#pragma unroll
    for (int b = 0; b < 8; b++) acc[b] = 0ll;

#pragma unroll
    for (int k = 0; k < 16; k++) {
        const unsigned byte = (sb[k >> 2] >> (8 * (k & 3))) & 0xFFu;
        const int w = wq[k];
#pragma unroll
        for (int b = 0; b < 8; b++) {
            const int yb = 1 - 2 * (int)((byte >> b) & 1u);
            acc[b] += (long long)w * yb;          // IMAD.WIDE
        }
    }

#pragma unroll
    for (int b = 0; b < 8; b++) {
#pragma unroll
        for (int off = 16; off > 0; off >>= 1)
            acc[b] += __shfl_down_sync(0xffffffffu, acc[b], off);
    }
    __shared__ long long red[8][8];
    if (lane == 0) {
#pragma unroll
        for (int b = 0; b < 8; b++) red[wid][b] = acc[b];
    }
    __syncthreads();
    if (tid < 8) {
        long long s = 0ll;
#pragma unroll
        for (int w2 = 0; w2 < 8; w2++) s += red[w2][tid];
        if (tid < B) g_z[tid * NN + row] = s;
    }
}

// ---------------------------------------------------------------------------
// Per-sample sequential state. Key pack:
// bits[0]=nb(=!y_sign), [1:13]=neuron i, [13:25]=pos-in-sweep.
// ---------------------------------------------------------------------------
struct SState {
    long long z[ZPT];      // fields, int64 scale 2^40
    int  ckey[ZPT];        // static per-sweep candidate keys
    int  zmask[ZPT];       // y_sign << 31 (static per sweep)
    int  specv[ZPT];       // speculative W row (2nd candidate)
    unsigned ym;           // bit k = (y[base+k] < 0)
    int  thr;              // position threshold (last winner key)
    int  sweep;            // current sweep; == iters -> done
    int  spec_id;          // neuron id held in specv, or -1
};

__device__ __forceinline__ void publish_min(SState& st, int* slot, int np,
                                            int lane, int wid)
{
    unsigned key = (unsigned)INF;
#pragma unroll
    for (int k = 0; k < ZPT; k++) {
        const int t = (int)(st.z[k] >> 32) ^ st.zmask[k];
        if (t < 0 && st.ckey[k] > st.thr) key = min(key, (unsigned)st.ckey[k]);
    }
    const unsigned wmin = __reduce_min_sync(0xffffffffu, key);
    if (lane == 0) slot[np * 16 + wid] = (int)wmin;
}

__device__ __forceinline__ void build_keys(SState& st,
                                           const unsigned short* posT,
                                           int base)
{
    const uint4 pp = *reinterpret_cast<const uint4*>(posT + base);
    const int pos[8] = { (int)(pp.x & 0xFFFFu), (int)(pp.x >> 16),
                         (int)(pp.y & 0xFFFFu), (int)(pp.y >> 16),
                         (int)(pp.z & 0xFFFFu), (int)(pp.z >> 16),
                         (int)(pp.w & 0xFFFFu), (int)(pp.w >> 16) };
#pragma unroll
    for (int k = 0; k < ZPT; k++) {
        const int yb = (int)((st.ym >> k) & 1u);
        st.ckey[k]  = (pos[k] << 13) | ((base + k) << 1) | (yb ^ 1);
        st.zmask[k] = yb << 31;
    }
    st.thr = -1;
}

__device__ __forceinline__ void round_step(SState& st, int* slot,
                                           const unsigned short* posT,
                                           int iters, int parity,
                                           int lane, int wid, int tid, int base)
{
    if (st.sweep >= iters) return;                 // done (block-uniform)
    const int a  = (lane < 16) ? slot[parity * 16 + lane] : INF;
    const int mk = (int)__reduce_min_sync(0xffffffffu, (unsigned)a);
    const int np = parity ^ 1;

    if (mk == INF) {                               // sweep transition
        st.sweep++;
        if (st.sweep >= iters) return;             // sample finished
        build_keys(st, posT + (size_t)st.sweep * NN, base);
        publish_min(st, slot, np, lane, wid);      // tables static: no barrier
        return;
    }

    const int e  = (a == mk) ? INF : a;
    const int r2 = (int)__reduce_min_sync(0xffffffffu, (unsigned)e);

    const int fi = (mk >> 1) & 0xFFF;
    const int nb = mk & 1;
    st.thr = mk;
    const int sfd = 2 - 4 * nb;                    // flip delta = +-2*wq

    // ---- axpy: one IMAD.WIDE per element ----
    if (fi == st.spec_id) {                        // uniform branch: spec hit
#pragma unroll
        for (int k = 0; k < ZPT; k++)
            st.z[k] += (long long)st.specv[k] * sfd;
    } else {                                       // miss: demand load
        const int4* w4 = reinterpret_cast<const int4*>(g_Wq + (size_t)fi * NN + base);
        const int4 da = __ldg(w4), db = __ldg(w4 + 1);
        const int dv[8] = {da.x, da.y, da.z, da.w, db.x, db.y, db.z, db.w};
#pragma unroll
        for (int k = 0; k < ZPT; k++)
            st.z[k] += (long long)dv[k] * sfd;
    }

    // ---- speculative register load of 2nd candidate's row ----
    const int nsid = (r2 != INF) ? ((r2 >> 1) & 0xFFF) : -1;
    if (nsid >= 0) {                               // uniform branch
        const int4* s4 = reinterpret_cast<const int4*>(g_Wq + (size_t)nsid * NN + base);
        const int4 sa = __ldg(s4), sb = __ldg(s4 + 1);
        st.specv[0] = sa.x; st.specv[1] = sa.y; st.specv[2] = sa.z; st.specv[3] = sa.w;
        st.specv[4] = sb.x; st.specv[5] = sb.y; st.specv[6] = sb.z; st.specv[7] = sb.w;
    }
    st.spec_id = nsid;

    // owner records the flip (stale ckey/zmask excluded by ckey > thr)
    if (tid == (fi >> 3)) st.ym ^= 1u << (fi & 7);

    publish_min(st, slot, np, lane, wid);
}

__device__ __forceinline__ void init_state(SState& st, const float* x, int s,
                                           int base)
{
    const long long* gz = g_z + (size_t)s * NN + base;
#pragma unroll
    for (int k = 0; k < ZPT; k++) st.z[k] = gz[k];
    const float4 xa = *reinterpret_cast<const float4*>(x + (size_t)s * NN + base);
    const float4 xb = *reinterpret_cast<const float4*>(x + (size_t)s * NN + base + 4);
    unsigned ym = 0;
    ym |= (__float_as_uint(xa.x) >> 31) << 0;
    ym |= (__float_as_uint(xa.y) >> 31) << 1;
    ym |= (__float_as_uint(xa.z) >> 31) << 2;
    ym |= (__float_as_uint(xa.w) >> 31) << 3;
    ym |= (__float_as_uint(xb.x) >> 31) << 4;
    ym |= (__float_as_uint(xb.y) >> 31) << 5;
    ym |= (__float_as_uint(xb.z) >> 31) << 6;
    ym |= (__float_as_uint(xb.w) >> 31) << 7;
    st.ym = ym; st.sweep = 0; st.thr = -1; st.spec_id = -1;
#pragma unroll
    for (int k = 0; k < ZPT; k++) st.specv[k] = 0;
}

__device__ __forceinline__ void build_pos_tables(const int* pb, int iters,
                                                 unsigned short* posT, int base)
{
    for (int s = 0; s < iters; s++) {
        const int4 a = *reinterpret_cast<const int4*>(pb + s * NN + base);
        const int4 c = *reinterpret_cast<const int4*>(pb + s * NN + base + 4);
        unsigned short* row = posT + (size_t)s * NN;
        row[a.x] = (unsigned short)(base + 0);
        row[a.y] = (unsigned short)(base + 1);
        row[a.z] = (unsigned short)(base + 2);
        row[a.w] = (unsigned short)(base + 3);
        row[c.x] = (unsigned short)(base + 4);
        row[c.y] = (unsigned short)(base + 5);
        row[c.z] = (unsigned short)(base + 6);
        row[c.w] = (unsigned short)(base + 7);
    }
}

__device__ __forceinline__ void write_out(float* out, int s, int base,
                                          unsigned ym)
{
    float4 o0, o1;
    o0.x = ((ym >> 0) & 1u) ? -1.0f : 1.0f;
    o0.y = ((ym >> 1) & 1u) ? -1.0f : 1.0f;
    o0.z = ((ym >> 2) & 1u) ? -1.0f : 1.0f;
    o0.w = ((ym >> 3) & 1u) ? -1.0f : 1.0f;
    o1.x = ((ym >> 4) & 1u) ? -1.0f : 1.0f;
    o1.y = ((ym >> 5) & 1u) ? -1.0f : 1.0f;
    o1.z = ((ym >> 6) & 1u) ? -1.0f : 1.0f;
    o1.w = ((ym >> 7) & 1u) ? -1.0f : 1.0f;
    *reinterpret_cast<float4*>(out + (size_t)s * NN + base)     = o0;
    *reinterpret_cast<float4*>(out + (size_t)s * NN + base + 4) = o1;
}

// ---------------------------------------------------------------------------
__global__ void __launch_bounds__(TPB, 1) hopfield_seq(
    const float* __restrict__ x,
    const int*   __restrict__ perms,
    float*       __restrict__ out,
    int iters, int B)
{
    extern __shared__ unsigned char smem[];
    int* slotA = reinterpret_cast<int*>(smem);                  // [2][16]
    int* slotB = reinterpret_cast<int*>(smem + 128);            // [2][16]
    unsigned short* posA = reinterpret_cast<unsigned short*>(smem + 256);
    unsigned short* posB = posA + (size_t)iters * NN;

    const int pair = blockIdx.x;
    const int sA   = pair * 2;
    const int sB   = sA + 1;
    const bool hasB = (sB < B);
    const int tid  = threadIdx.x;
    const int lane = tid & 31;
    const int wid  = tid >> 5;             // 16 warps
    const int base = tid * ZPT;

    // ---- build all-sweep neuron->position tables (written once) ----
    build_pos_tables(perms + (size_t)sA * iters * NN, iters, posA, base);
    if (hasB)
        build_pos_tables(perms + (size_t)sB * iters * NN, iters, posB, base);

    SState stA, stB;
    init_state(stA, x, sA, base);
    if (hasB) init_state(stB, x, sB, base);
    else      { stB.sweep = iters; stB.ym = 0; stB.thr = -1; stB.spec_id = -1; }

    __syncthreads();                       // pos tables visible

    build_keys(stA, posA, base);           // sweep 0
    publish_min(stA, slotA, 0, lane, wid);
    if (hasB) {
        build_keys(stB, posB, base);
        publish_min(stB, slotB, 0, lane, wid);
    }
    __syncthreads();

    int parity = 0;
    while (stA.sweep < iters || stB.sweep < iters) {
        round_step(stA, slotA, posA, iters, parity, lane, wid, tid, base);
        round_step(stB, slotB, posB, iters, parity, lane, wid, tid, base);
        __syncthreads();                   // the single shared barrier
        parity ^= 1;
    }

    write_out(out, sA, base, stA.ym);
    if (hasB) write_out(out, sB, base, stB.ym);
}

// ---------------------------------------------------------------------------
extern "C" void kernel_launch(void* const* d_in, const int* in_sizes, int n_in,
                              void* d_out, int out_size)
{
    const float* x     = (const float*)d_in[0];
    const float* W     = (const float*)d_in[1];
    const int*   perms = (const int*)  d_in[2];
    float*       out   = (float*)d_out;

    const int B     = in_sizes[0] / NN;
    const int iters = in_sizes[2] / in_sizes[0];

    const size_t shmem = 256 + 2 * (size_t)iters * NN * sizeof(unsigned short);
    cudaFuncSetAttribute(hopfield_seq,
                         cudaFuncAttributeMaxDynamicSharedMemorySize,
                         (int)shmem);     // idempotent host-side config

    prep_wq<<<NN * NN / (256 * 16), 256>>>(W, x, B);
    gemv_init<<<NN, 256>>>(B);
    hopfield_seq<<<(B + 1) / 2, TPB, shmem>>>(x, perms, out, iters, B);
}

// round 16
// speedup vs baseline: 1.9202x; 1.9202x over previous
#include <cuda_runtime.h>

// HopfieldNetwork: B=8, N=4096, ITERS=10 asynchronous sweeps.
// R16 = R13 (best: 1267us) revert + micro-opts:
//  (1) TWO register spec rows: r2 -> specv, r3 -> specv2 (replacing r3's L1
//      prefetch: same line traffic, but a 3rd-ranked winner now costs 0
//      instead of an L1 hit).
//  (2) prep_wq fused into gemv_init (one fewer full pass over W).
//  (3) slot array padded to 32 with INF so decode reads slot[lane] with no
//      predicate.
// R14 (TPB=1024), R15 (2 samples/block), R11/R12 (dual-flip) all measured
// worse -- per-thread state multiplication and decode replication both lose.
// z int64 scale 2^40; wq = rn(W*2^40); flip delta = +-2*wq via IMAD.WIDE.

constexpr int NN  = 4096;
constexpr int TPB = 512;
constexpr int ZPT = 8;
constexpr int INF = 0x7FFFFFFF;

__device__ long long g_z[8 * NN];                      // z, int64, scale 2^40
__device__ __align__(16) int g_Wq[NN * NN];            // rn(W * 2^40)
__device__ __align__(16) unsigned char g_xsign[NN];    // bit b = (x[b][c] < 0)

// ---------------------------------------------------------------------------
// Kernel 0: pack x signs (one byte per column).
// ---------------------------------------------------------------------------
__global__ void pack_x(const float* __restrict__ x, int B)
{
    const int c = blockIdx.x * 256 + threadIdx.x;
    unsigned v = 0;
#pragma unroll
    for (int b = 0; b < 8; b++)
        if (b < B && x[(size_t)b * NN + c] < 0.f) v |= 1u << b;
    g_xsign[c] = (unsigned char)v;
}

// ---------------------------------------------------------------------------
// Kernel 1 (fused): quantize one W row, store g_Wq, and compute
// z0[b][row] = sum_c wq[row][c]*y[b][c] in the same pass. One block per row.
// ---------------------------------------------------------------------------
__global__ void __launch_bounds__(256) gemv_prep(const float* __restrict__ W,
                                                 int B)
{
    const int row  = blockIdx.x;
    const int tid  = threadIdx.x;
    const int base = tid * 16;
    const int lane = tid & 31, wid = tid >> 5;

    // quantize 16 elements of this row
    const float4* w4 = reinterpret_cast<const float4*>(W + (size_t)row * NN + base);
    int wq[16];
#pragma unroll
    for (int g = 0; g < 4; g++) {
        const float4 v = w4[g];
        wq[4 * g + 0] = __float2int_rn(v.x * 0x1.0p40f);
        wq[4 * g + 1] = __float2int_rn(v.y * 0x1.0p40f);
        wq[4 * g + 2] = __float2int_rn(v.z * 0x1.0p40f);
        wq[4 * g + 3] = __float2int_rn(v.w * 0x1.0p40f);
    }
    int4* o4 = reinterpret_cast<int4*>(g_Wq + (size_t)row * NN + base);
#pragma unroll
    for (int g = 0; g < 4; g++)
        o4[g] = make_int4(wq[4 * g + 0], wq[4 * g + 1], wq[4 * g + 2], wq[4 * g + 3]);

    // dot products against packed x signs
    const uint4 sb4 = *reinterpret_cast<const uint4*>(g_xsign + base);
    const unsigned sb[4] = {sb4.x, sb4.y, sb4.z, sb4.w};

    long long acc[8];
#pragma unroll
    for (int b = 0; b < 8; b++) acc[b] = 0ll;

#pragma unroll
    for (int k = 0; k < 16; k++) {
        const unsigned byte = (sb[k >> 2] >> (8 * (k & 3))) & 0xFFu;
        const int w = wq[k];
#pragma unroll
        for (int b = 0; b < 8; b++) {
            const int yb = 1 - 2 * (int)((byte >> b) & 1u);
            acc[b] += (long long)w * yb;          // IMAD.WIDE
        }
    }

#pragma unroll
    for (int b = 0; b < 8; b++) {
#pragma unroll
        for (int off = 16; off > 0; off >>= 1)
            acc[b] += __shfl_down_sync(0xffffffffu, acc[b], off);
    }
    __shared__ long long red[8][8];
    if (lane == 0) {
#pragma unroll
        for (int b = 0; b < 8; b++) red[wid][b] = acc[b];
    }
    __syncthreads();
    if (tid < 8) {
        long long s = 0ll;
#pragma unroll
        for (int w2 = 0; w2 < 8; w2++) s += red[w2][tid];
        if (tid < B) g_z[tid * NN + row] = s;
    }
}

// ---------------------------------------------------------------------------
// Kernel 2: one block per sample, one barrier per flip.
// Key pack: bits[0]=nb(=!y_sign), [1:13]=neuron i, [13:25]=pos-in-sweep.
// ---------------------------------------------------------------------------
__global__ void __launch_bounds__(TPB, 1) hopfield_seq(
    const float* __restrict__ x,
    const int*   __restrict__ perms,
    float*       __restrict__ out,
    int iters)
{
    const int b    = blockIdx.x;
    const int tid  = threadIdx.x;
    const int lane = tid & 31;
    const int wid  = tid >> 5;          // 16 warps
    const int base = tid * ZPT;

    __shared__ __align__(16) unsigned short pos_of[NN];   // neuron -> pos
    __shared__ __align__(16) int sh_slot[2][32];          // upper 16 = INF pad

    if (tid < 32) { sh_slot[0][tid] = INF; sh_slot[1][tid] = INF; }

    // ---- load z slice and x signs into registers ----
    long long z[ZPT];
    {
        const long long* gz = g_z + (size_t)b * NN + base;
#pragma unroll
        for (int k = 0; k < ZPT; k++) z[k] = gz[k];
    }

    unsigned ym = 0;   // bit k = (y[base+k] < 0)
    {
        const float4* x4 = reinterpret_cast<const float4*>(x + (size_t)b * NN + base);
#pragma unroll
        for (int g = 0; g < 2; g++) {
            const float4 xv = x4[g];
            ym |= (__float_as_uint(xv.x) >> 31) << (4 * g + 0);
            ym |= (__float_as_uint(xv.y) >> 31) << (4 * g + 1);
            ym |= (__float_as_uint(xv.z) >> 31) << (4 * g + 2);
            ym |= (__float_as_uint(xv.w) >> 31) << (4 * g + 3);
        }
    }

    const int* pb = perms + (size_t)b * iters * NN;
    int parity   = 0;
    int spec_id  = -1, spec_id2 = -1;    // neurons held in specv / specv2
    int specv[ZPT], specv2[ZPT];
#pragma unroll
    for (int k = 0; k < ZPT; k++) { specv[k] = 0; specv2[k] = 0; }

    for (int sweep = 0; sweep < iters; sweep++) {
        // ---- build neuron -> position table for this sweep ----
        const int* ps = pb + sweep * NN;
        {
            const int4* p4 = reinterpret_cast<const int4*>(ps + tid * 8);
#pragma unroll
            for (int g = 0; g < 2; g++) {
                const int4 a = p4[g];
                const int p0 = tid * 8 + g * 4;
                pos_of[a.x] = (unsigned short)(p0 + 0);
                pos_of[a.y] = (unsigned short)(p0 + 1);
                pos_of[a.z] = (unsigned short)(p0 + 2);
                pos_of[a.w] = (unsigned short)(p0 + 3);
            }
        }
        __syncthreads();                         // pos_of visible

        // ---- static per-sweep candidate keys + sign-xor masks ----
        int ckey[ZPT];      // (pos<<13)|(neuron<<1)|(!y_sign)
        int zmask[ZPT];     // y_sign << 31
#pragma unroll
        for (int k = 0; k < ZPT; k++) {
            const int yb = (int)((ym >> k) & 1u);
            ckey[k]  = ((int)pos_of[base + k] << 13) | ((base + k) << 1) | (yb ^ 1);
            zmask[k] = yb << 31;
        }

        int thr = -1;

        // ---- initial candidates for this sweep ----
        {
            unsigned key = (unsigned)INF;
#pragma unroll
            for (int k = 0; k < ZPT; k++) {
                const int t = (int)(z[k] >> 32) ^ zmask[k];
                if (t < 0) key = min(key, (unsigned)ckey[k]);
            }
            const unsigned wmin = __reduce_min_sync(0xffffffffu, key);
            if (lane == 0) sh_slot[parity][wid] = (int)wmin;
        }
        __syncthreads();                         // slots visible

        // ---- flip rounds: one barrier each ----
        for (;;) {
            // lane-parallel decode: one slot per lane (padded), redux top-3
            const int a  = sh_slot[parity][lane];
            parity ^= 1;
            const int mk = (int)__reduce_min_sync(0xffffffffu, (unsigned)a);
            if (mk == INF) break;                // sweep finished

            const int e  = (a == mk) ? INF : a;
            const int r2 = (int)__reduce_min_sync(0xffffffffu, (unsigned)e);

            const int fi = (mk >> 1) & 0xFFF;
            const int nb = mk & 1;
            thr = mk;

            // flip delta is +-2*W at scale 2^40 -> add +-2*wq
            const int sfd = 2 - 4 * nb;

            // ---- axpy: one IMAD.WIDE per element (register rows preferred) ----
            if (fi == spec_id) {                 // uniform: primary spec hit
#pragma unroll
                for (int k = 0; k < ZPT; k++)
                    z[k] += (long long)specv[k] * sfd;
            } else if (fi == spec_id2) {         // uniform: secondary spec hit
#pragma unroll
                for (int k = 0; k < ZPT; k++)
                    z[k] += (long long)specv2[k] * sfd;
            } else {                             // miss: demand load
                const int4* w4 =
                    reinterpret_cast<const int4*>(g_Wq + (size_t)fi * NN + base);
                const int4 da = __ldg(w4 + 0), db = __ldg(w4 + 1);
                const int dv[ZPT] = {da.x, da.y, da.z, da.w,
                                     db.x, db.y, db.z, db.w};
#pragma unroll
                for (int k = 0; k < ZPT; k++)
                    z[k] += (long long)dv[k] * sfd;
            }

            // ---- next-round speculation: r2 -> specv, r3 -> specv2 ----
            {
                const int e3 = (e == r2) ? INF : e;
                const int r3 = (int)__reduce_min_sync(0xffffffffu, (unsigned)e3);

                const int n1 = (r2 != INF) ? ((r2 >> 1) & 0xFFF) : -1;
                if (n1 >= 0) {                   // uniform branch
                    const int4* s4 =
                        reinterpret_cast<const int4*>(g_Wq + (size_t)n1 * NN + base);
                    const int4 sa = __ldg(s4 + 0), sb_ = __ldg(s4 + 1);
                    specv[0] = sa.x;  specv[1] = sa.y;  specv[2] = sa.z;  specv[3] = sa.w;
                    specv[4] = sb_.x; specv[5] = sb_.y; specv[6] = sb_.z; specv[7] = sb_.w;
                }
                spec_id = n1;

                const int n2 = (r3 != INF) ? ((r3 >> 1) & 0xFFF) : -1;
                if (n2 >= 0) {                   // uniform branch
                    const int4* s4 =
                        reinterpret_cast<const int4*>(g_Wq + (size_t)n2 * NN + base);
                    const int4 sa = __ldg(s4 + 0), sb_ = __ldg(s4 + 1);
                    specv2[0] = sa.x;  specv2[1] = sa.y;  specv2[2] = sa.z;  specv2[3] = sa.w;
                    specv2[4] = sb_.x; specv2[5] = sb_.y; specv2[6] = sb_.z; specv2[7] = sb_.w;
                }
                spec_id2 = n2;
            }

            // owner records the flip (stale ckey/zmask excluded by ckey > thr)
            if (tid == (fi >> 3)) ym ^= 1u << (fi & 7);

            // ---- candidate regeneration: static keys, sign-xor test ----
            {
                unsigned key = (unsigned)INF;
#pragma unroll
                for (int k = 0; k < ZPT; k++) {
                    const int t = (int)(z[k] >> 32) ^ zmask[k];
                    if (t < 0 && ckey[k] > thr) key = min(key, (unsigned)ckey[k]);
                }
                const unsigned wmin = __reduce_min_sync(0xffffffffu, key);
                if (lane == 0) sh_slot[parity][wid] = (int)wmin;
            }
            __syncthreads();                     // the single barrier
        }
    }

    // ---- write y from register state ----
    float4* o4 = reinterpret_cast<float4*>(out + (size_t)b * NN + base);
#pragma unroll
    for (int g = 0; g < 2; g++) {
        float4 o;
        o.x = ((ym >> (4 * g + 0)) & 1u) ? -1.0f : 1.0f;
        o.y = ((ym >> (4 * g + 1)) & 1u) ? -1.0f : 1.0f;
        o.z = ((ym >> (4 * g + 2)) & 1u) ? -1.0f : 1.0f;
        o.w = ((ym >> (4 * g + 3)) & 1u) ? -1.0f : 1.0f;
        o4[g] = o;
    }
}

// ---------------------------------------------------------------------------
extern "C" void kernel_launch(void* const* d_in, const int* in_sizes, int n_in,
                              void* d_out, int out_size)
{
    const float* x     = (const float*)d_in[0];
    const float* W     = (const float*)d_in[1];
    const int*   perms = (const int*)  d_in[2];
    float*       out   = (float*)d_out;

    const int B     = in_sizes[0] / NN;
    const int iters = in_sizes[2] / in_sizes[0];

    pack_x<<<NN / 256, 256>>>(x, B);
    gemv_prep<<<NN, 256>>>(W, B);
    hopfield_seq<<<B, TPB>>>(x, perms, out, iters);
}